// round 10
// baseline (speedup 1.0000x reference)
#include <cuda_runtime.h>

// ---------------------------------------------------------------------------
// WaveConv3d: 2-level db4 3D DWT (periodic, pad 8) -> per-voxel channel mix on
// the 8 coarsest bands -> inverse DWT (level-1 details zero -> lo-only).
// R10: level-2 inverse x-IDWT fused into the zy kernel (i2x_zy, dynamic smem),
// mirroring the proven i1x_yz pattern. Eliminates the 4x(320,37,23,23)
// intermediate (569MB -> 322MB for that stage).
// ---------------------------------------------------------------------------

#define NV 12167            // 23^3

#define FLO {-0.010597401784997278f,  0.032883011666982945f,  0.030841381835986965f, \
             -0.18703481171888114f,  -0.02798376941698385f,   0.6308807679295904f,  \
              0.7148465705525415f,    0.23037781330885523f}
#define FHI { 0.23037781330885523f,  -0.7148465705525415f,    0.6308807679295904f,  \
              0.02798376941698385f,  -0.18703481171888114f,  -0.030841381835986965f,\
              0.032883011666982945f,  0.010597401784997278f}

// Scratch (max live = 8 bands * 320*23^3 = 31.1M floats)
__device__ float g_buf1[31147520];
__device__ float g_buf2[31147520];

// ---------------------------------------------------------------------------
// Forward DWT along a strided axis (x-pass). One thread per row, sliding window.
// ---------------------------------------------------------------------------
template<int N, int INNER, bool HI>
__global__ void dwt_s(const float* __restrict__ in, float* __restrict__ olo,
                      float* __restrict__ ohi, unsigned total) {
    constexpr int K = (N + 8) / 2 + 1;
    const float LO[8] = FLO;
    const float HIc[8] = FHI;
    unsigned g = blockIdx.x * blockDim.x + threadIdx.x;
    if (g >= total) return;
    unsigned ii = g % INNER;
    unsigned o  = g / INNER;
    const float* bp = in  + (size_t)o * (N * INNER) + ii;
    float*       lp = olo + (size_t)o * (K * INNER) + ii;
    float*       hp = HI ? ohi + (size_t)o * (K * INNER) + ii : nullptr;

    float w[8];
#pragma unroll
    for (int t = 0; t < 8; t++) w[t] = bp[(N - 8 + t) * INNER];

#pragma unroll
    for (int j = 0; j < K; j++) {
        float alo = 0.f, ahi = 0.f;
#pragma unroll
        for (int t = 0; t < 8; t++) {
            alo = fmaf(w[t], LO[7 - t], alo);
            if (HI) ahi = fmaf(w[t], HIc[7 - t], ahi);
        }
        lp[j * INNER] = alo;
        if (HI) hp[j * INNER] = ahi;
        if (j < K - 1) {
            int q0 = (2 * j) % N;
            int q1 = (2 * j + 1) % N;
#pragma unroll
            for (int t = 0; t < 6; t++) w[t] = w[t + 2];
            w[6] = bp[q0 * INNER];
            w[7] = bp[q1 * INNER];
        }
    }
}

// ---------------------------------------------------------------------------
// Level-1 forward, fused y+z, lo-only, paired outputs (R5 version).
// ---------------------------------------------------------------------------
__global__ void f1_yz(const float* __restrict__ in, float* __restrict__ out) {
    __shared__ float s0[64 * 64];
    __shared__ float s1[37 * 65];
    const float LO[8] = FLO;
    unsigned tid = threadIdx.x;
    size_t blk = blockIdx.x;
    const float* gp = in + blk * 4096;
#pragma unroll 4
    for (int t = tid; t < 4096; t += 256) s0[t] = gp[t];
    __syncthreads();
    for (int u = tid; u < 19 * 64; u += 256) {       // y-DWT pairs
        int z = u & 63, jp = u >> 6;
        float w[10];
#pragma unroll
        for (int t = 0; t < 10; t++) {
            int q = (4 * jp - 8 + t) & 63;
            w[t] = s0[q * 64 + z];
        }
        float a0 = 0.f, a1 = 0.f;
#pragma unroll
        for (int s = 0; s < 8; s++) {
            a0 = fmaf(LO[s], w[7 - s], a0);
            a1 = fmaf(LO[s], w[9 - s], a1);
        }
        s1[(2 * jp) * 65 + z] = a0;
        if (2 * jp + 1 < 37) s1[(2 * jp + 1) * 65 + z] = a1;
    }
    __syncthreads();
    float* op = out + blk * 1369;
    for (int u = tid; u < 37 * 19; u += 256) {       // z-DWT pairs
        int ph = u % 19, y = u / 19;
        float w[10];
#pragma unroll
        for (int t = 0; t < 10; t++) {
            int q = (4 * ph - 8 + t) & 63;
            w[t] = s1[y * 65 + q];
        }
        float a0 = 0.f, a1 = 0.f;
#pragma unroll
        for (int s = 0; s < 8; s++) {
            a0 = fmaf(LO[s], w[7 - s], a0);
            a1 = fmaf(LO[s], w[9 - s], a1);
        }
        op[y * 37 + 2 * ph] = a0;
        if (2 * ph + 1 < 37) op[y * 37 + 2 * ph + 1] = a1;
    }
}

// ---------------------------------------------------------------------------
// Level-2 forward, fused y+z, full (4 yz-bands), paired (R5 version).
// ---------------------------------------------------------------------------
__global__ void f2_yz(const float* __restrict__ in, float* __restrict__ out,
                      long long S2) {
    __shared__ float s0[37 * 37];
    __shared__ float sl[23 * 37];
    __shared__ float sh[23 * 37];
    const float LO[8] = FLO;
    const float HIc[8] = FHI;
    unsigned tid = threadIdx.x;
    size_t blk = blockIdx.x;
    const float* gp = in + blk * 1369;
#pragma unroll 3
    for (int t = tid; t < 1369; t += 256) s0[t] = gp[t];
    __syncthreads();
    for (int u = tid; u < 12 * 37; u += 256) {       // y-DWT lo+hi pairs
        int z = u % 37, jp = u / 37;
        float w[10];
#pragma unroll
        for (int t = 0; t < 10; t++) {
            int q = 4 * jp - 8 + t;
            if (q < 0) q += 37; else if (q >= 37) q -= 37;
            w[t] = s0[q * 37 + z];
        }
        float l0 = 0.f, h0 = 0.f, l1 = 0.f, h1 = 0.f;
#pragma unroll
        for (int s = 0; s < 8; s++) {
            l0 = fmaf(LO[s],  w[7 - s], l0);
            h0 = fmaf(HIc[s], w[7 - s], h0);
            l1 = fmaf(LO[s],  w[9 - s], l1);
            h1 = fmaf(HIc[s], w[9 - s], h1);
        }
        sl[(2 * jp) * 37 + z] = l0;
        sh[(2 * jp) * 37 + z] = h0;
        if (2 * jp + 1 < 23) {
            sl[(2 * jp + 1) * 37 + z] = l1;
            sh[(2 * jp + 1) * 37 + z] = h1;
        }
    }
    __syncthreads();
    for (int u = tid; u < 23 * 12; u += 256) {       // z-DWT pairs on both
        int ph = u % 12, y = u / 12;
        float wl[10], wh[10];
#pragma unroll
        for (int t = 0; t < 10; t++) {
            int q = 4 * ph - 8 + t;
            if (q < 0) q += 37; else if (q >= 37) q -= 37;
            wl[t] = sl[y * 37 + q];
            wh[t] = sh[y * 37 + q];
        }
        float ll0 = 0.f, lh0 = 0.f, hl0 = 0.f, hh0 = 0.f;
        float ll1 = 0.f, lh1 = 0.f, hl1 = 0.f, hh1 = 0.f;
#pragma unroll
        for (int s = 0; s < 8; s++) {
            ll0 = fmaf(LO[s],  wl[7 - s], ll0);  lh0 = fmaf(HIc[s], wl[7 - s], lh0);
            hl0 = fmaf(LO[s],  wh[7 - s], hl0);  hh0 = fmaf(HIc[s], wh[7 - s], hh0);
            ll1 = fmaf(LO[s],  wl[9 - s], ll1);  lh1 = fmaf(HIc[s], wl[9 - s], lh1);
            hl1 = fmaf(LO[s],  wh[9 - s], hl1);  hh1 = fmaf(HIc[s], wh[9 - s], hh1);
        }
        size_t b0 = blk * 529 + y * 23 + 2 * ph;
        out[b0]          = ll0;
        out[S2 + b0]     = lh0;
        out[2 * S2 + b0] = hl0;
        out[3 * S2 + b0] = hh0;
        if (2 * ph + 1 < 23) {
            out[b0 + 1]          = ll1;
            out[S2 + b0 + 1]     = lh1;
            out[2 * S2 + b0 + 1] = hl1;
            out[3 * S2 + b0 + 1] = hh1;
        }
    }
}

// ---------------------------------------------------------------------------
// Level-2 inverse, FUSED x+z+y. One block per (bc, xb), xb in [0,10):
// output x-slices xo = 4xb..min(4xb+3,36). Loads the 5 shared source x-slices
// (js in [2xb+1, 2xb+5]) for all 8 bands (84.6KB, coalesced), then per xo:
// x-IDWT (lo=band m, hi=band 4+m) -> z-IDWT -> y-IDWT -> direct write.
// Replaces idwt_s<23,37,529> + i2_yz. Dynamic smem ~100KB.
// ---------------------------------------------------------------------------
__global__ void i2x_zy(const float* __restrict__ in, float* __restrict__ out,
                       long long SBl) {
    extern __shared__ float sm[];
    float* ss = sm;                  // [5 slices][8 bands][529]
    float* si = sm + 21160;          // [4 yz-slots][529]
    float* sl = si + 2116;           // [23*37]
    float* sh = sl + 851;            // [23*37]
    const float LO[8] = FLO;
    const float HIc[8] = FHI;
    unsigned tid = threadIdx.x;
    unsigned bc = blockIdx.x / 10;
    unsigned xb = blockIdx.x % 10;
    int j0 = 2 * (int)xb + 1;

    for (int t = tid; t < 5 * 8 * 529; t += 256) {
        int r = t % 529;
        int k = (t / 529) & 7;
        int sidx = t / (529 * 8);
        int j = j0 + sidx;
        if (j <= 22)
            ss[t] = in[(size_t)k * SBl + ((size_t)bc * 23 + j) * 529 + r];
    }
    __syncthreads();

    for (int c = 0; c < 4; c++) {
        int xo = 4 * (int)xb + c;
        if (xo > 36) break;
        int par = c & 1;
        int off = c >> 1;            // js = xo/2+1 = j0 + off

        // x-IDWT: si[m][r] = sum_d ss[off+d][m][r]*fl + ss[off+d][4+m][r]*fh
        for (int u = tid; u < 4 * 529; u += 256) {
            int r = u % 529, m = u / 529;
            float a = 0.f;
#pragma unroll
            for (int d = 0; d < 4; d++) {
                float fl = par ? LO[2 * d] : LO[2 * d + 1];
                float fh = par ? HIc[2 * d] : HIc[2 * d + 1];
                a = fmaf(ss[((off + d) * 8 + m) * 529 + r],     fl, a);
                a = fmaf(ss[((off + d) * 8 + 4 + m) * 529 + r], fh, a);
            }
            si[u] = a;
        }
        __syncthreads();

        // z-IDWT, both dy rows, paired (i2_yz stage).
        for (int u = tid; u < 23 * 19; u += 256) {
            int m = u % 19, y = u / 19;
            int js = m + 1;
            float a0 = 0.f, a1 = 0.f, b0 = 0.f, b1 = 0.f;
#pragma unroll
            for (int d = 0; d < 4; d++) {
                int q = y * 23 + js + d;
                float v0 = si[q],           v1 = si[529 + q];
                float v2 = si[2 * 529 + q], v3 = si[3 * 529 + q];
                a0 = fmaf(v0, LO[2 * d + 1], a0);  a0 = fmaf(v1, HIc[2 * d + 1], a0);
                a1 = fmaf(v0, LO[2 * d],     a1);  a1 = fmaf(v1, HIc[2 * d],     a1);
                b0 = fmaf(v2, LO[2 * d + 1], b0);  b0 = fmaf(v3, HIc[2 * d + 1], b0);
                b1 = fmaf(v2, LO[2 * d],     b1);  b1 = fmaf(v3, HIc[2 * d],     b1);
            }
            sl[y * 37 + 2 * m] = a0;  sh[y * 37 + 2 * m] = b0;
            if (2 * m + 1 < 37) {
                sl[y * 37 + 2 * m + 1] = a1;  sh[y * 37 + 2 * m + 1] = b1;
            }
        }
        __syncthreads();

        // y-IDWT, paired; direct write to (bc, xo) slice of the intermediate.
        float* op = out + ((size_t)bc * 37 + xo) * 1369;
        for (int u = tid; u < 19 * 37; u += 256) {
            int z = u % 37, m = u / 37;
            int js = m + 1;
            float a0 = 0.f, a1 = 0.f;
#pragma unroll
            for (int d = 0; d < 4; d++) {
                float vl = sl[(js + d) * 37 + z];
                float vh = sh[(js + d) * 37 + z];
                a0 = fmaf(vl, LO[2 * d + 1], a0);  a0 = fmaf(vh, HIc[2 * d + 1], a0);
                a1 = fmaf(vl, LO[2 * d],     a1);  a1 = fmaf(vh, HIc[2 * d],     a1);
            }
            op[(2 * m) * 37 + z] = a0;
            if (2 * m + 1 < 37) op[(2 * m + 1) * 37 + z] = a1;
        }
        __syncthreads();
    }
}

// ---------------------------------------------------------------------------
// Level-1 inverse, FUSED x+z+y, lo-only (R9 version, proven).
// ---------------------------------------------------------------------------
__global__ void i1x_yz(const float* __restrict__ in, float* __restrict__ out) {
    __shared__ float ss[5 * 1369];
    __shared__ float s0[1369];
    __shared__ float s1[37 * 65];
    const float LO[8] = FLO;
    unsigned tid = threadIdx.x;
    unsigned bc = blockIdx.x >> 4;
    unsigned xb = blockIdx.x & 15;
    int j0 = 2 * (int)xb + 1;

    const float* gp = in + ((size_t)bc * 37 + j0) * 1369;
#pragma unroll 2
    for (int t = tid; t < 5 * 1369; t += 256) ss[t] = gp[t];
    __syncthreads();

#pragma unroll
    for (int c = 0; c < 4; c++) {
        int xo  = 4 * (int)xb + c;
        int par = c & 1;
        int off = (c >> 1) * 1369;

        for (int t = tid; t < 1369; t += 256) {
            float a = 0.f;
#pragma unroll
            for (int d = 0; d < 4; d++) {
                float fl = par ? LO[2 * d] : LO[2 * d + 1];
                a = fmaf(ss[off + d * 1369 + t], fl, a);
            }
            s0[t] = a;
        }
        __syncthreads();

        for (int u = tid; u < 37 * 32; u += 256) {
            int m = u & 31, y = u >> 5;
            int js = m + 1;
            float a0 = 0.f, a1 = 0.f;
#pragma unroll
            for (int d = 0; d < 4; d++) {
                float v = s0[y * 37 + js + d];
                a0 = fmaf(v, LO[2 * d + 1], a0);
                a1 = fmaf(v, LO[2 * d],     a1);
            }
            s1[y * 65 + 2 * m]     = a0;
            s1[y * 65 + 2 * m + 1] = a1;
        }
        __syncthreads();

        float* op = out + ((size_t)bc * 64 + xo) * 4096;
        for (int u = tid; u < 32 * 64; u += 256) {
            int z = u & 63, m = u >> 6;
            int js = m + 1;
            float a0 = 0.f, a1 = 0.f;
#pragma unroll
            for (int d = 0; d < 4; d++) {
                float v = s1[(js + d) * 65 + z];
                a0 = fmaf(v, LO[2 * d + 1], a0);
                a1 = fmaf(v, LO[2 * d],     a1);
            }
            op[(2 * m) * 64 + z]     = a0;
            op[(2 * m + 1) * 64 + z] = a1;
        }
        __syncthreads();
    }
}

// ---------------------------------------------------------------------------
// Channel mix, ALL 8 bands in one launch (blockIdx.y = band).
// ---------------------------------------------------------------------------
__global__ void chanmix_all(const float* __restrict__ in,
                            float* __restrict__ out, long long SBl,
                            const float* __restrict__ w0, const float* __restrict__ w1,
                            const float* __restrict__ w2, const float* __restrict__ w3,
                            const float* __restrict__ w4, const float* __restrict__ w5,
                            const float* __restrict__ w6, const float* __restrict__ w7) {
    __shared__ float s_in[320][32];
    int k = blockIdx.y;
    const float* w;
    switch (k) {
        case 0: w = w0; break; case 1: w = w1; break;
        case 2: w = w2; break; case 3: w = w3; break;
        case 4: w = w4; break; case 5: w = w5; break;
        case 6: w = w6; break; default: w = w7; break;
    }
    const float* bin  = in  + (long long)k * SBl;
    float*       bout = out + (long long)k * SBl;

    int lane = threadIdx.x;
    int ty   = threadIdx.y;
    int v    = blockIdx.x * 32 + lane;
    bool valid = v < NV;
    int vc = valid ? v : (NV - 1);

    for (int r = ty; r < 320; r += 8)
        s_in[r][lane] = bin[(long long)r * NV + vc];
    __syncthreads();

    float acc[5][8];
#pragma unroll
    for (int a = 0; a < 5; a++)
#pragma unroll
        for (int b = 0; b < 8; b++) acc[a][b] = 0.f;

#pragma unroll 2
    for (int i = 0; i < 40; i += 2) {
        float xv0[8], xv1[8];
#pragma unroll
        for (int b = 0; b < 8; b++) {
            xv0[b] = s_in[b * 40 + i][lane];
            xv1[b] = s_in[b * 40 + i + 1][lane];
        }
        float wv0[5], wv1[5];
#pragma unroll
        for (int oo = 0; oo < 5; oo++) {
            int o = ty + oo * 8;
            wv0[oo] = w[((long long)i * 40 + o) * NV + vc];
            wv1[oo] = w[((long long)(i + 1) * 40 + o) * NV + vc];
        }
#pragma unroll
        for (int oo = 0; oo < 5; oo++)
#pragma unroll
            for (int b = 0; b < 8; b++) {
                acc[oo][b] = fmaf(xv0[b], wv0[oo], acc[oo][b]);
                acc[oo][b] = fmaf(xv1[b], wv1[oo], acc[oo][b]);
            }
    }
    if (!valid) return;
#pragma unroll
    for (int oo = 0; oo < 5; oo++) {
        int o = ty + oo * 8;
#pragma unroll
        for (int b = 0; b < 8; b++)
            bout[((long long)b * 40 + o) * NV + v] = acc[oo][b];
    }
}

// ---------------------------------------------------------------------------
extern "C" void kernel_launch(void* const* d_in, const int* in_sizes, int n_in,
                              void* d_out, int out_size) {
    const float* x = (const float*)d_in[0];
    float* out = (float*)d_out;

    float *b1, *b2;
    cudaGetSymbolAddress((void**)&b1, g_buf1);
    cudaGetSymbolAddress((void**)&b2, g_buf2);

    const long long S2  = 6263360LL;   // 320*37*23*23 (per yz-band volume)
    const long long SBl = 3893440LL;   // 320*23*23*23 (per final band volume)
    const int I2X_SMEM = (21160 + 2116 + 851 + 851) * 4;   // 99,912 bytes

    static bool attr_done = false;
    if (!attr_done) {
        cudaFuncSetAttribute(i2x_zy, cudaFuncAttributeMaxDynamicSharedMemorySize,
                             I2X_SMEM);
        attr_done = true;
    }

    auto g = [](unsigned t) { return (t + 255u) / 256u; };

    // --- Level-1 forward: fused yz (lo), then x (lo) ------------------------
    f1_yz<<<320 * 64, 256>>>(x, b1);                        // -> (320,64,37,37)
    { unsigned T = 320u * 1369u;                            // -> (320,37,37,37)
      dwt_s<64, 1369, false><<<g(T), 256>>>(b1, b2, nullptr, T); }

    // --- Level-2 forward: fused yz (4 bands), then x (lo+hi over all 4) -----
    f2_yz<<<320 * 37, 256>>>(b2, b1, S2);                   // -> 4x(320,37,23,23)
    { unsigned T = 1280u * 529u;                            // -> 8x(320,23,23,23)
      dwt_s<37, 529, true><<<g(T), 256>>>(b1, b2, b2 + 4 * SBl, T); }

    // --- Channel mix: all 8 bands in one launch (slot == weight index k) ----
    chanmix_all<<<dim3((NV + 31) / 32, 8), dim3(32, 8)>>>(
        b2, b1, SBl,
        (const float*)d_in[1], (const float*)d_in[2],
        (const float*)d_in[3], (const float*)d_in[4],
        (const float*)d_in[5], (const float*)d_in[6],
        (const float*)d_in[7], (const float*)d_in[8]);

    // --- Level-2 inverse: FUSED x+zy over all 8 bands ------------------------
    i2x_zy<<<320 * 10, 256, I2X_SMEM>>>(b1, b2, SBl);       // -> (320,37,37,37)

    // --- Level-1 inverse: FUSED x+zy (lo), no intermediate ------------------
    i1x_yz<<<320 * 16, 256>>>(b2, out);                     // -> (320,64,64,64)
}

// round 11
// speedup vs baseline: 1.3957x; 1.3957x over previous
#include <cuda_runtime.h>

// ---------------------------------------------------------------------------
// WaveConv3d: 2-level db4 3D DWT (periodic, pad 8) -> per-voxel channel mix on
// the 8 coarsest bands -> inverse DWT (level-1 details zero -> lo-only).
// R11: revert level-2 inverse to the proven R9 two-kernel form (the 100KB-smem
// fused kernel collapsed occupancy); widen i1x_yz to 8 output slices per block
// (7 shared source slices, 53KB smem, 4 blocks/SM) to trim redundant reads.
// ---------------------------------------------------------------------------

#define NV 12167            // 23^3

#define FLO {-0.010597401784997278f,  0.032883011666982945f,  0.030841381835986965f, \
             -0.18703481171888114f,  -0.02798376941698385f,   0.6308807679295904f,  \
              0.7148465705525415f,    0.23037781330885523f}
#define FHI { 0.23037781330885523f,  -0.7148465705525415f,    0.6308807679295904f,  \
              0.02798376941698385f,  -0.18703481171888114f,  -0.030841381835986965f,\
              0.032883011666982945f,  0.010597401784997278f}

// Scratch (max live = 8 bands * 320*23^3 = 31.1M floats)
__device__ float g_buf1[31147520];
__device__ float g_buf2[31147520];

// ---------------------------------------------------------------------------
// Forward DWT along a strided axis (x-pass). One thread per row, sliding window.
// ---------------------------------------------------------------------------
template<int N, int INNER, bool HI>
__global__ void dwt_s(const float* __restrict__ in, float* __restrict__ olo,
                      float* __restrict__ ohi, unsigned total) {
    constexpr int K = (N + 8) / 2 + 1;
    const float LO[8] = FLO;
    const float HIc[8] = FHI;
    unsigned g = blockIdx.x * blockDim.x + threadIdx.x;
    if (g >= total) return;
    unsigned ii = g % INNER;
    unsigned o  = g / INNER;
    const float* bp = in  + (size_t)o * (N * INNER) + ii;
    float*       lp = olo + (size_t)o * (K * INNER) + ii;
    float*       hp = HI ? ohi + (size_t)o * (K * INNER) + ii : nullptr;

    float w[8];
#pragma unroll
    for (int t = 0; t < 8; t++) w[t] = bp[(N - 8 + t) * INNER];

#pragma unroll
    for (int j = 0; j < K; j++) {
        float alo = 0.f, ahi = 0.f;
#pragma unroll
        for (int t = 0; t < 8; t++) {
            alo = fmaf(w[t], LO[7 - t], alo);
            if (HI) ahi = fmaf(w[t], HIc[7 - t], ahi);
        }
        lp[j * INNER] = alo;
        if (HI) hp[j * INNER] = ahi;
        if (j < K - 1) {
            int q0 = (2 * j) % N;
            int q1 = (2 * j + 1) % N;
#pragma unroll
            for (int t = 0; t < 6; t++) w[t] = w[t + 2];
            w[6] = bp[q0 * INNER];
            w[7] = bp[q1 * INNER];
        }
    }
}

// ---------------------------------------------------------------------------
// Inverse DWT along a strided axis (x-pass, level-2). No wrap needed.
// ---------------------------------------------------------------------------
template<int K, int NOUT, int INNER, bool HI>
__global__ void idwt_s(const float* __restrict__ lo, const float* __restrict__ hi,
                       float* __restrict__ out, unsigned total) {
    const float LO[8] = FLO;
    const float HIc[8] = FHI;
    unsigned g = blockIdx.x * blockDim.x + threadIdx.x;
    if (g >= total) return;
    unsigned ii = g % INNER;
    unsigned o  = g / INNER;
    const float* lp = lo + (size_t)o * (K * INNER) + ii;
    const float* hp = HI ? hi + (size_t)o * (K * INNER) + ii : lp;
    float*       op = out + (size_t)o * (NOUT * INNER) + ii;

    float wl[4], wh[4];
#pragma unroll
    for (int d = 0; d < 4; d++) {
        wl[d] = lp[(1 + d) * INNER];
        if (HI) wh[d] = hp[(1 + d) * INNER];
    }
#pragma unroll
    for (int i = 0; i < NOUT; i++) {
        const int par = i & 1;
        float acc = 0.f;
#pragma unroll
        for (int d = 0; d < 4; d++) {
            acc = fmaf(wl[d], LO[2 * d + 1 - par], acc);
            if (HI) acc = fmaf(wh[d], HIc[2 * d + 1 - par], acc);
        }
        op[i * INNER] = acc;
        if (par && (i + 1 < NOUT)) {
            int jn = i / 2 + 5;
#pragma unroll
            for (int d = 0; d < 3; d++) {
                wl[d] = wl[d + 1];
                if (HI) wh[d] = wh[d + 1];
            }
            wl[3] = lp[jn * INNER];
            if (HI) wh[3] = hp[jn * INNER];
        }
    }
}

// ---------------------------------------------------------------------------
// Level-1 forward, fused y+z, lo-only, paired outputs (R5 version).
// ---------------------------------------------------------------------------
__global__ void f1_yz(const float* __restrict__ in, float* __restrict__ out) {
    __shared__ float s0[64 * 64];
    __shared__ float s1[37 * 65];
    const float LO[8] = FLO;
    unsigned tid = threadIdx.x;
    size_t blk = blockIdx.x;
    const float* gp = in + blk * 4096;
#pragma unroll 4
    for (int t = tid; t < 4096; t += 256) s0[t] = gp[t];
    __syncthreads();
    for (int u = tid; u < 19 * 64; u += 256) {       // y-DWT pairs
        int z = u & 63, jp = u >> 6;
        float w[10];
#pragma unroll
        for (int t = 0; t < 10; t++) {
            int q = (4 * jp - 8 + t) & 63;
            w[t] = s0[q * 64 + z];
        }
        float a0 = 0.f, a1 = 0.f;
#pragma unroll
        for (int s = 0; s < 8; s++) {
            a0 = fmaf(LO[s], w[7 - s], a0);
            a1 = fmaf(LO[s], w[9 - s], a1);
        }
        s1[(2 * jp) * 65 + z] = a0;
        if (2 * jp + 1 < 37) s1[(2 * jp + 1) * 65 + z] = a1;
    }
    __syncthreads();
    float* op = out + blk * 1369;
    for (int u = tid; u < 37 * 19; u += 256) {       // z-DWT pairs
        int ph = u % 19, y = u / 19;
        float w[10];
#pragma unroll
        for (int t = 0; t < 10; t++) {
            int q = (4 * ph - 8 + t) & 63;
            w[t] = s1[y * 65 + q];
        }
        float a0 = 0.f, a1 = 0.f;
#pragma unroll
        for (int s = 0; s < 8; s++) {
            a0 = fmaf(LO[s], w[7 - s], a0);
            a1 = fmaf(LO[s], w[9 - s], a1);
        }
        op[y * 37 + 2 * ph] = a0;
        if (2 * ph + 1 < 37) op[y * 37 + 2 * ph + 1] = a1;
    }
}

// ---------------------------------------------------------------------------
// Level-2 forward, fused y+z, full (4 yz-bands), paired (R5 version).
// ---------------------------------------------------------------------------
__global__ void f2_yz(const float* __restrict__ in, float* __restrict__ out,
                      long long S2) {
    __shared__ float s0[37 * 37];
    __shared__ float sl[23 * 37];
    __shared__ float sh[23 * 37];
    const float LO[8] = FLO;
    const float HIc[8] = FHI;
    unsigned tid = threadIdx.x;
    size_t blk = blockIdx.x;
    const float* gp = in + blk * 1369;
#pragma unroll 3
    for (int t = tid; t < 1369; t += 256) s0[t] = gp[t];
    __syncthreads();
    for (int u = tid; u < 12 * 37; u += 256) {       // y-DWT lo+hi pairs
        int z = u % 37, jp = u / 37;
        float w[10];
#pragma unroll
        for (int t = 0; t < 10; t++) {
            int q = 4 * jp - 8 + t;
            if (q < 0) q += 37; else if (q >= 37) q -= 37;
            w[t] = s0[q * 37 + z];
        }
        float l0 = 0.f, h0 = 0.f, l1 = 0.f, h1 = 0.f;
#pragma unroll
        for (int s = 0; s < 8; s++) {
            l0 = fmaf(LO[s],  w[7 - s], l0);
            h0 = fmaf(HIc[s], w[7 - s], h0);
            l1 = fmaf(LO[s],  w[9 - s], l1);
            h1 = fmaf(HIc[s], w[9 - s], h1);
        }
        sl[(2 * jp) * 37 + z] = l0;
        sh[(2 * jp) * 37 + z] = h0;
        if (2 * jp + 1 < 23) {
            sl[(2 * jp + 1) * 37 + z] = l1;
            sh[(2 * jp + 1) * 37 + z] = h1;
        }
    }
    __syncthreads();
    for (int u = tid; u < 23 * 12; u += 256) {       // z-DWT pairs on both
        int ph = u % 12, y = u / 12;
        float wl[10], wh[10];
#pragma unroll
        for (int t = 0; t < 10; t++) {
            int q = 4 * ph - 8 + t;
            if (q < 0) q += 37; else if (q >= 37) q -= 37;
            wl[t] = sl[y * 37 + q];
            wh[t] = sh[y * 37 + q];
        }
        float ll0 = 0.f, lh0 = 0.f, hl0 = 0.f, hh0 = 0.f;
        float ll1 = 0.f, lh1 = 0.f, hl1 = 0.f, hh1 = 0.f;
#pragma unroll
        for (int s = 0; s < 8; s++) {
            ll0 = fmaf(LO[s],  wl[7 - s], ll0);  lh0 = fmaf(HIc[s], wl[7 - s], lh0);
            hl0 = fmaf(LO[s],  wh[7 - s], hl0);  hh0 = fmaf(HIc[s], wh[7 - s], hh0);
            ll1 = fmaf(LO[s],  wl[9 - s], ll1);  lh1 = fmaf(HIc[s], wl[9 - s], lh1);
            hl1 = fmaf(LO[s],  wh[9 - s], hl1);  hh1 = fmaf(HIc[s], wh[9 - s], hh1);
        }
        size_t b0 = blk * 529 + y * 23 + 2 * ph;
        out[b0]          = ll0;
        out[S2 + b0]     = lh0;
        out[2 * S2 + b0] = hl0;
        out[3 * S2 + b0] = hh0;
        if (2 * ph + 1 < 23) {
            out[b0 + 1]          = ll1;
            out[S2 + b0 + 1]     = lh1;
            out[2 * S2 + b0 + 1] = hl1;
            out[3 * S2 + b0 + 1] = hh1;
        }
    }
}

// ---------------------------------------------------------------------------
// Level-2 inverse, fused z+y, full, paired (R5/R9 version).
// ---------------------------------------------------------------------------
__global__ void i2_yz(const float* __restrict__ in, float* __restrict__ out,
                      long long S2) {
    __shared__ float si[4 * 529];
    __shared__ float sl[23 * 37];
    __shared__ float sh[23 * 37];
    const float LO[8] = FLO;
    const float HIc[8] = FHI;
    unsigned tid = threadIdx.x;
    size_t blk = blockIdx.x;
    for (int t = tid; t < 4 * 529; t += 256) {
        int slot = t / 529, r = t % 529;
        si[t] = in[(size_t)slot * S2 + blk * 529 + r];
    }
    __syncthreads();
    for (int u = tid; u < 23 * 19; u += 256) {       // z-IDWT, both dy rows
        int m = u % 19, y = u / 19;
        int js = m + 1;
        float a0 = 0.f, a1 = 0.f, b0 = 0.f, b1 = 0.f;
#pragma unroll
        for (int d = 0; d < 4; d++) {
            int q = y * 23 + js + d;
            float v0 = si[q],           v1 = si[529 + q];
            float v2 = si[2 * 529 + q], v3 = si[3 * 529 + q];
            a0 = fmaf(v0, LO[2 * d + 1], a0);  a0 = fmaf(v1, HIc[2 * d + 1], a0);
            a1 = fmaf(v0, LO[2 * d],     a1);  a1 = fmaf(v1, HIc[2 * d],     a1);
            b0 = fmaf(v2, LO[2 * d + 1], b0);  b0 = fmaf(v3, HIc[2 * d + 1], b0);
            b1 = fmaf(v2, LO[2 * d],     b1);  b1 = fmaf(v3, HIc[2 * d],     b1);
        }
        sl[y * 37 + 2 * m] = a0;  sh[y * 37 + 2 * m] = b0;
        if (2 * m + 1 < 37) {
            sl[y * 37 + 2 * m + 1] = a1;  sh[y * 37 + 2 * m + 1] = b1;
        }
    }
    __syncthreads();
    float* op = out + blk * 1369;
    for (int u = tid; u < 19 * 37; u += 256) {       // y-IDWT pairs
        int z = u % 37, m = u / 37;
        int js = m + 1;
        float a0 = 0.f, a1 = 0.f;
#pragma unroll
        for (int d = 0; d < 4; d++) {
            float vl = sl[(js + d) * 37 + z];
            float vh = sh[(js + d) * 37 + z];
            a0 = fmaf(vl, LO[2 * d + 1], a0);  a0 = fmaf(vh, HIc[2 * d + 1], a0);
            a1 = fmaf(vl, LO[2 * d],     a1);  a1 = fmaf(vh, HIc[2 * d],     a1);
        }
        op[(2 * m) * 37 + z] = a0;
        if (2 * m + 1 < 37) op[(2 * m + 1) * 37 + z] = a1;
    }
}

// ---------------------------------------------------------------------------
// Level-1 inverse, FUSED x+z+y, lo-only. One block per (bc, xb), xb in [0,8):
// 8 output x-slices xo = 8xb..8xb+7 from 7 shared source slices
// (js union = [4xb+1, 4xb+7]). 53KB smem -> 4 blocks/SM.
// ---------------------------------------------------------------------------
__global__ void i1x_yz(const float* __restrict__ in, float* __restrict__ out) {
    __shared__ float ss[7 * 1369];   // 7 source x-slices (37y x 37z each)
    __shared__ float s0[1369];       // x-combined slice for current xo
    __shared__ float s1[37 * 65];    // z-IDWT result (37y x 64z, padded)
    const float LO[8] = FLO;
    unsigned tid = threadIdx.x;
    unsigned bc = blockIdx.x >> 3;
    unsigned xb = blockIdx.x & 7;
    int j0 = 4 * (int)xb + 1;              // first source slice (max 29; +6 = 35)

    const float* gp = in + ((size_t)bc * 37 + j0) * 1369;
#pragma unroll 2
    for (int t = tid; t < 7 * 1369; t += 256) ss[t] = gp[t];   // coalesced
    __syncthreads();

#pragma unroll
    for (int c = 0; c < 8; c++) {
        int xo  = 8 * (int)xb + c;
        int par = c & 1;
        int off = (c >> 1) * 1369;         // js = xo/2+1 = j0 + (c>>1)

        // x-IDWT: s0[t] = sum_d ss[off + d*1369 + t] * LO[2d+1-par]
        for (int t = tid; t < 1369; t += 256) {
            float a = 0.f;
#pragma unroll
            for (int d = 0; d < 4; d++) {
                float fl = par ? LO[2 * d] : LO[2 * d + 1];
                a = fmaf(ss[off + d * 1369 + t], fl, a);
            }
            s0[t] = a;
        }
        __syncthreads();

        // z-IDWT, paired: 37 y x 32 pairs.
        for (int u = tid; u < 37 * 32; u += 256) {
            int m = u & 31, y = u >> 5;
            int js = m + 1;
            float a0 = 0.f, a1 = 0.f;
#pragma unroll
            for (int d = 0; d < 4; d++) {
                float v = s0[y * 37 + js + d];
                a0 = fmaf(v, LO[2 * d + 1], a0);
                a1 = fmaf(v, LO[2 * d],     a1);
            }
            s1[y * 65 + 2 * m]     = a0;
            s1[y * 65 + 2 * m + 1] = a1;
        }
        __syncthreads();

        // y-IDWT, paired: 32 pairs x 64 z; direct coalesced output write.
        float* op = out + ((size_t)bc * 64 + xo) * 4096;
        for (int u = tid; u < 32 * 64; u += 256) {
            int z = u & 63, m = u >> 6;
            int js = m + 1;
            float a0 = 0.f, a1 = 0.f;
#pragma unroll
            for (int d = 0; d < 4; d++) {
                float v = s1[(js + d) * 65 + z];
                a0 = fmaf(v, LO[2 * d + 1], a0);
                a1 = fmaf(v, LO[2 * d],     a1);
            }
            op[(2 * m) * 64 + z]     = a0;
            op[(2 * m + 1) * 64 + z] = a1;
        }
        __syncthreads();
    }
}

// ---------------------------------------------------------------------------
// Channel mix, ALL 8 bands in one launch (blockIdx.y = band).
// ---------------------------------------------------------------------------
__global__ void chanmix_all(const float* __restrict__ in,
                            float* __restrict__ out, long long SBl,
                            const float* __restrict__ w0, const float* __restrict__ w1,
                            const float* __restrict__ w2, const float* __restrict__ w3,
                            const float* __restrict__ w4, const float* __restrict__ w5,
                            const float* __restrict__ w6, const float* __restrict__ w7) {
    __shared__ float s_in[320][32];
    int k = blockIdx.y;
    const float* w;
    switch (k) {
        case 0: w = w0; break; case 1: w = w1; break;
        case 2: w = w2; break; case 3: w = w3; break;
        case 4: w = w4; break; case 5: w = w5; break;
        case 6: w = w6; break; default: w = w7; break;
    }
    const float* bin  = in  + (long long)k * SBl;
    float*       bout = out + (long long)k * SBl;

    int lane = threadIdx.x;
    int ty   = threadIdx.y;
    int v    = blockIdx.x * 32 + lane;
    bool valid = v < NV;
    int vc = valid ? v : (NV - 1);

    for (int r = ty; r < 320; r += 8)
        s_in[r][lane] = bin[(long long)r * NV + vc];
    __syncthreads();

    float acc[5][8];
#pragma unroll
    for (int a = 0; a < 5; a++)
#pragma unroll
        for (int b = 0; b < 8; b++) acc[a][b] = 0.f;

#pragma unroll 2
    for (int i = 0; i < 40; i += 2) {
        float xv0[8], xv1[8];
#pragma unroll
        for (int b = 0; b < 8; b++) {
            xv0[b] = s_in[b * 40 + i][lane];
            xv1[b] = s_in[b * 40 + i + 1][lane];
        }
        float wv0[5], wv1[5];
#pragma unroll
        for (int oo = 0; oo < 5; oo++) {
            int o = ty + oo * 8;
            wv0[oo] = w[((long long)i * 40 + o) * NV + vc];
            wv1[oo] = w[((long long)(i + 1) * 40 + o) * NV + vc];
        }
#pragma unroll
        for (int oo = 0; oo < 5; oo++)
#pragma unroll
            for (int b = 0; b < 8; b++) {
                acc[oo][b] = fmaf(xv0[b], wv0[oo], acc[oo][b]);
                acc[oo][b] = fmaf(xv1[b], wv1[oo], acc[oo][b]);
            }
    }
    if (!valid) return;
#pragma unroll
    for (int oo = 0; oo < 5; oo++) {
        int o = ty + oo * 8;
#pragma unroll
        for (int b = 0; b < 8; b++)
            bout[((long long)b * 40 + o) * NV + v] = acc[oo][b];
    }
}

// ---------------------------------------------------------------------------
extern "C" void kernel_launch(void* const* d_in, const int* in_sizes, int n_in,
                              void* d_out, int out_size) {
    const float* x = (const float*)d_in[0];
    float* out = (float*)d_out;

    float *b1, *b2;
    cudaGetSymbolAddress((void**)&b1, g_buf1);
    cudaGetSymbolAddress((void**)&b2, g_buf2);

    const long long S2  = 6263360LL;   // 320*37*23*23 (per yz-band volume)
    const long long SBl = 3893440LL;   // 320*23*23*23 (per final band volume)

    auto g = [](unsigned t) { return (t + 255u) / 256u; };

    // --- Level-1 forward: fused yz (lo), then x (lo) ------------------------
    f1_yz<<<320 * 64, 256>>>(x, b1);                        // -> (320,64,37,37)
    { unsigned T = 320u * 1369u;                            // -> (320,37,37,37)
      dwt_s<64, 1369, false><<<g(T), 256>>>(b1, b2, nullptr, T); }

    // --- Level-2 forward: fused yz (4 bands), then x (lo+hi over all 4) -----
    f2_yz<<<320 * 37, 256>>>(b2, b1, S2);                   // -> 4x(320,37,23,23)
    { unsigned T = 1280u * 529u;                            // -> 8x(320,23,23,23)
      dwt_s<37, 529, true><<<g(T), 256>>>(b1, b2, b2 + 4 * SBl, T); }

    // --- Channel mix: all 8 bands in one launch (slot == weight index k) ----
    chanmix_all<<<dim3((NV + 31) / 32, 8), dim3(32, 8)>>>(
        b2, b1, SBl,
        (const float*)d_in[1], (const float*)d_in[2],
        (const float*)d_in[3], (const float*)d_in[4],
        (const float*)d_in[5], (const float*)d_in[6],
        (const float*)d_in[7], (const float*)d_in[8]);

    // --- Level-2 inverse: x (lo+hi over all 4), then fused zy ---------------
    { unsigned T = 1280u * 529u;                            // -> 4x(320,37,23,23)
      idwt_s<23, 37, 529, true><<<g(T), 256>>>(b1, b1 + 4 * SBl, b2, T); }
    i2_yz<<<320 * 37, 256>>>(b2, b1, S2);                   // -> (320,37,37,37)

    // --- Level-1 inverse: FUSED x+zy (lo), 8 slices/block --------------------
    i1x_yz<<<320 * 8, 256>>>(b1, out);                      // -> (320,64,64,64)
}

// round 12
// speedup vs baseline: 1.4465x; 1.0364x over previous
#include <cuda_runtime.h>

// ---------------------------------------------------------------------------
// WaveConv3d: 2-level db4 3D DWT (periodic, pad 8) -> per-voxel channel mix on
// the 8 coarsest bands -> inverse DWT (level-1 details zero -> lo-only).
// R12: R9 base (proven 659us). Level-2 inverse re-fused the occupancy-safe
// way: x-IDWT streamed from global into registers (no slice staging), smem
// 30.5KB -> 7 blocks/SM. Removes idwt_s<23,37,529> + its 100MB intermediate.
// ---------------------------------------------------------------------------

#define NV 12167            // 23^3

#define FLO {-0.010597401784997278f,  0.032883011666982945f,  0.030841381835986965f, \
             -0.18703481171888114f,  -0.02798376941698385f,   0.6308807679295904f,  \
              0.7148465705525415f,    0.23037781330885523f}
#define FHI { 0.23037781330885523f,  -0.7148465705525415f,    0.6308807679295904f,  \
              0.02798376941698385f,  -0.18703481171888114f,  -0.030841381835986965f,\
              0.032883011666982945f,  0.010597401784997278f}

// Scratch (max live = 8 bands * 320*23^3 = 31.1M floats)
__device__ float g_buf1[31147520];
__device__ float g_buf2[31147520];

// ---------------------------------------------------------------------------
// Forward DWT along a strided axis (x-pass). One thread per row, sliding window.
// ---------------------------------------------------------------------------
template<int N, int INNER, bool HI>
__global__ void dwt_s(const float* __restrict__ in, float* __restrict__ olo,
                      float* __restrict__ ohi, unsigned total) {
    constexpr int K = (N + 8) / 2 + 1;
    const float LO[8] = FLO;
    const float HIc[8] = FHI;
    unsigned g = blockIdx.x * blockDim.x + threadIdx.x;
    if (g >= total) return;
    unsigned ii = g % INNER;
    unsigned o  = g / INNER;
    const float* bp = in  + (size_t)o * (N * INNER) + ii;
    float*       lp = olo + (size_t)o * (K * INNER) + ii;
    float*       hp = HI ? ohi + (size_t)o * (K * INNER) + ii : nullptr;

    float w[8];
#pragma unroll
    for (int t = 0; t < 8; t++) w[t] = bp[(N - 8 + t) * INNER];

#pragma unroll
    for (int j = 0; j < K; j++) {
        float alo = 0.f, ahi = 0.f;
#pragma unroll
        for (int t = 0; t < 8; t++) {
            alo = fmaf(w[t], LO[7 - t], alo);
            if (HI) ahi = fmaf(w[t], HIc[7 - t], ahi);
        }
        lp[j * INNER] = alo;
        if (HI) hp[j * INNER] = ahi;
        if (j < K - 1) {
            int q0 = (2 * j) % N;
            int q1 = (2 * j + 1) % N;
#pragma unroll
            for (int t = 0; t < 6; t++) w[t] = w[t + 2];
            w[6] = bp[q0 * INNER];
            w[7] = bp[q1 * INNER];
        }
    }
}

// ---------------------------------------------------------------------------
// Level-1 forward, fused y+z, lo-only, paired outputs (R5 version).
// ---------------------------------------------------------------------------
__global__ void f1_yz(const float* __restrict__ in, float* __restrict__ out) {
    __shared__ float s0[64 * 64];
    __shared__ float s1[37 * 65];
    const float LO[8] = FLO;
    unsigned tid = threadIdx.x;
    size_t blk = blockIdx.x;
    const float* gp = in + blk * 4096;
#pragma unroll 4
    for (int t = tid; t < 4096; t += 256) s0[t] = gp[t];
    __syncthreads();
    for (int u = tid; u < 19 * 64; u += 256) {       // y-DWT pairs
        int z = u & 63, jp = u >> 6;
        float w[10];
#pragma unroll
        for (int t = 0; t < 10; t++) {
            int q = (4 * jp - 8 + t) & 63;
            w[t] = s0[q * 64 + z];
        }
        float a0 = 0.f, a1 = 0.f;
#pragma unroll
        for (int s = 0; s < 8; s++) {
            a0 = fmaf(LO[s], w[7 - s], a0);
            a1 = fmaf(LO[s], w[9 - s], a1);
        }
        s1[(2 * jp) * 65 + z] = a0;
        if (2 * jp + 1 < 37) s1[(2 * jp + 1) * 65 + z] = a1;
    }
    __syncthreads();
    float* op = out + blk * 1369;
    for (int u = tid; u < 37 * 19; u += 256) {       // z-DWT pairs
        int ph = u % 19, y = u / 19;
        float w[10];
#pragma unroll
        for (int t = 0; t < 10; t++) {
            int q = (4 * ph - 8 + t) & 63;
            w[t] = s1[y * 65 + q];
        }
        float a0 = 0.f, a1 = 0.f;
#pragma unroll
        for (int s = 0; s < 8; s++) {
            a0 = fmaf(LO[s], w[7 - s], a0);
            a1 = fmaf(LO[s], w[9 - s], a1);
        }
        op[y * 37 + 2 * ph] = a0;
        if (2 * ph + 1 < 37) op[y * 37 + 2 * ph + 1] = a1;
    }
}

// ---------------------------------------------------------------------------
// Level-2 forward, fused y+z, full (4 yz-bands), paired (R5 version).
// ---------------------------------------------------------------------------
__global__ void f2_yz(const float* __restrict__ in, float* __restrict__ out,
                      long long S2) {
    __shared__ float s0[37 * 37];
    __shared__ float sl[23 * 37];
    __shared__ float sh[23 * 37];
    const float LO[8] = FLO;
    const float HIc[8] = FHI;
    unsigned tid = threadIdx.x;
    size_t blk = blockIdx.x;
    const float* gp = in + blk * 1369;
#pragma unroll 3
    for (int t = tid; t < 1369; t += 256) s0[t] = gp[t];
    __syncthreads();
    for (int u = tid; u < 12 * 37; u += 256) {       // y-DWT lo+hi pairs
        int z = u % 37, jp = u / 37;
        float w[10];
#pragma unroll
        for (int t = 0; t < 10; t++) {
            int q = 4 * jp - 8 + t;
            if (q < 0) q += 37; else if (q >= 37) q -= 37;
            w[t] = s0[q * 37 + z];
        }
        float l0 = 0.f, h0 = 0.f, l1 = 0.f, h1 = 0.f;
#pragma unroll
        for (int s = 0; s < 8; s++) {
            l0 = fmaf(LO[s],  w[7 - s], l0);
            h0 = fmaf(HIc[s], w[7 - s], h0);
            l1 = fmaf(LO[s],  w[9 - s], l1);
            h1 = fmaf(HIc[s], w[9 - s], h1);
        }
        sl[(2 * jp) * 37 + z] = l0;
        sh[(2 * jp) * 37 + z] = h0;
        if (2 * jp + 1 < 23) {
            sl[(2 * jp + 1) * 37 + z] = l1;
            sh[(2 * jp + 1) * 37 + z] = h1;
        }
    }
    __syncthreads();
    for (int u = tid; u < 23 * 12; u += 256) {       // z-DWT pairs on both
        int ph = u % 12, y = u / 12;
        float wl[10], wh[10];
#pragma unroll
        for (int t = 0; t < 10; t++) {
            int q = 4 * ph - 8 + t;
            if (q < 0) q += 37; else if (q >= 37) q -= 37;
            wl[t] = sl[y * 37 + q];
            wh[t] = sh[y * 37 + q];
        }
        float ll0 = 0.f, lh0 = 0.f, hl0 = 0.f, hh0 = 0.f;
        float ll1 = 0.f, lh1 = 0.f, hl1 = 0.f, hh1 = 0.f;
#pragma unroll
        for (int s = 0; s < 8; s++) {
            ll0 = fmaf(LO[s],  wl[7 - s], ll0);  lh0 = fmaf(HIc[s], wl[7 - s], lh0);
            hl0 = fmaf(LO[s],  wh[7 - s], hl0);  hh0 = fmaf(HIc[s], wh[7 - s], hh0);
            ll1 = fmaf(LO[s],  wl[9 - s], ll1);  lh1 = fmaf(HIc[s], wl[9 - s], lh1);
            hl1 = fmaf(LO[s],  wh[9 - s], hl1);  hh1 = fmaf(HIc[s], wh[9 - s], hh1);
        }
        size_t b0 = blk * 529 + y * 23 + 2 * ph;
        out[b0]          = ll0;
        out[S2 + b0]     = lh0;
        out[2 * S2 + b0] = hl0;
        out[3 * S2 + b0] = hh0;
        if (2 * ph + 1 < 23) {
            out[b0 + 1]          = ll1;
            out[S2 + b0 + 1]     = lh1;
            out[2 * S2 + b0 + 1] = hl1;
            out[3 * S2 + b0 + 1] = hh1;
        }
    }
}

// ---------------------------------------------------------------------------
// Level-2 inverse, FUSED x+z+y, register-streamed x-IDWT (occupancy-safe).
// Block = (bc, xb), xb in [0,10): output x-slices xo = 4xb..min(4xb+3,36),
// processed as two xo-PAIRS. Both parities of a pair share the same 4-tap js
// window, so each element needs 8 coalesced global loads (lo band m, hi band
// 4+m, d=0..3) producing si_even and si_odd directly — no slice staging.
// smem = 2*2116 + 4*851 = 30.5KB -> 7 blocks/SM. Writes (320,37,37,37).
// ---------------------------------------------------------------------------
__global__ void i2x_zy(const float* __restrict__ in, float* __restrict__ out,
                       long long SBl) {
    __shared__ float sie[4 * 529];
    __shared__ float sio[4 * 529];
    __shared__ float sle[23 * 37], she[23 * 37];
    __shared__ float slo[23 * 37], sho[23 * 37];
    const float LO[8] = FLO;
    const float HIc[8] = FHI;
    unsigned tid = threadIdx.x;
    unsigned bc = blockIdx.x / 10;
    unsigned xb = blockIdx.x % 10;

    for (int c = 0; c < 2; c++) {
        int xo0 = 4 * (int)xb + 2 * c;           // even; pair = (xo0, xo0+1)
        if (xo0 > 36) break;
        int js = 2 * (int)xb + 1 + c;            // <= 19; js+3 <= 22 in-range

        // x-IDWT streamed from global: element (k=m lo, k=4+m hi, js+d, r).
        for (int u = tid; u < 4 * 529; u += 256) {
            int m = u / 529, r = u % 529;
            const float* lp = in + (size_t)m * SBl
                              + (size_t)bc * 12167 + (size_t)js * 529 + r;
            const float* hp = lp + 4 * SBl;
            float ae = 0.f, ao = 0.f;
#pragma unroll
            for (int d = 0; d < 4; d++) {
                float vl = lp[d * 529];
                float vh = hp[d * 529];
                ae = fmaf(vl, LO[2 * d + 1], ae);  ae = fmaf(vh, HIc[2 * d + 1], ae);
                ao = fmaf(vl, LO[2 * d],     ao);  ao = fmaf(vh, HIc[2 * d],     ao);
            }
            sie[u] = ae;
            sio[u] = ao;
        }
        __syncthreads();

        // z-IDWT, both parities, both dy rows, paired outputs.
        for (int u = tid; u < 2 * 23 * 19; u += 256) {
            int p  = u / 437;                    // parity (0: xo0, 1: xo0+1)
            int v2 = u % 437;
            int m  = v2 % 19, y = v2 / 19;
            const float* si = p ? sio : sie;
            float* sl = p ? slo : sle;
            float* sh = p ? sho : she;
            int jz = m + 1;
            float a0 = 0.f, a1 = 0.f, b0 = 0.f, b1 = 0.f;
#pragma unroll
            for (int d = 0; d < 4; d++) {
                int q = y * 23 + jz + d;
                float v0 = si[q],           v1 = si[529 + q];
                float v2f = si[2 * 529 + q], v3 = si[3 * 529 + q];
                a0 = fmaf(v0, LO[2 * d + 1], a0);  a0 = fmaf(v1, HIc[2 * d + 1], a0);
                a1 = fmaf(v0, LO[2 * d],     a1);  a1 = fmaf(v1, HIc[2 * d],     a1);
                b0 = fmaf(v2f, LO[2 * d + 1], b0); b0 = fmaf(v3, HIc[2 * d + 1], b0);
                b1 = fmaf(v2f, LO[2 * d],     b1); b1 = fmaf(v3, HIc[2 * d],     b1);
            }
            sl[y * 37 + 2 * m] = a0;  sh[y * 37 + 2 * m] = b0;
            if (2 * m + 1 < 37) {
                sl[y * 37 + 2 * m + 1] = a1;  sh[y * 37 + 2 * m + 1] = b1;
            }
        }
        __syncthreads();

        // y-IDWT, both parities; direct write to (bc, xo) output slices.
        for (int u = tid; u < 2 * 19 * 37; u += 256) {
            int p  = u / 703;
            int xo = xo0 + p;
            if (xo > 36) continue;
            int v2 = u % 703;
            int z  = v2 % 37, m = v2 / 37;
            const float* sl = p ? slo : sle;
            const float* sh = p ? sho : she;
            int jy = m + 1;
            float a0 = 0.f, a1 = 0.f;
#pragma unroll
            for (int d = 0; d < 4; d++) {
                float vl = sl[(jy + d) * 37 + z];
                float vh = sh[(jy + d) * 37 + z];
                a0 = fmaf(vl, LO[2 * d + 1], a0);  a0 = fmaf(vh, HIc[2 * d + 1], a0);
                a1 = fmaf(vl, LO[2 * d],     a1);  a1 = fmaf(vh, HIc[2 * d],     a1);
            }
            float* op = out + ((size_t)bc * 37 + xo) * 1369;
            op[(2 * m) * 37 + z] = a0;
            if (2 * m + 1 < 37) op[(2 * m + 1) * 37 + z] = a1;
        }
        __syncthreads();
    }
}

// ---------------------------------------------------------------------------
// Level-1 inverse, FUSED x+z+y, lo-only (R9 version: 5 slices, 4 outputs).
// ---------------------------------------------------------------------------
__global__ void i1x_yz(const float* __restrict__ in, float* __restrict__ out) {
    __shared__ float ss[5 * 1369];
    __shared__ float s0[1369];
    __shared__ float s1[37 * 65];
    const float LO[8] = FLO;
    unsigned tid = threadIdx.x;
    unsigned bc = blockIdx.x >> 4;
    unsigned xb = blockIdx.x & 15;
    int j0 = 2 * (int)xb + 1;

    const float* gp = in + ((size_t)bc * 37 + j0) * 1369;
#pragma unroll 2
    for (int t = tid; t < 5 * 1369; t += 256) ss[t] = gp[t];
    __syncthreads();

#pragma unroll
    for (int c = 0; c < 4; c++) {
        int xo  = 4 * (int)xb + c;
        int par = c & 1;
        int off = (c >> 1) * 1369;

        for (int t = tid; t < 1369; t += 256) {
            float a = 0.f;
#pragma unroll
            for (int d = 0; d < 4; d++) {
                float fl = par ? LO[2 * d] : LO[2 * d + 1];
                a = fmaf(ss[off + d * 1369 + t], fl, a);
            }
            s0[t] = a;
        }
        __syncthreads();

        for (int u = tid; u < 37 * 32; u += 256) {
            int m = u & 31, y = u >> 5;
            int js = m + 1;
            float a0 = 0.f, a1 = 0.f;
#pragma unroll
            for (int d = 0; d < 4; d++) {
                float v = s0[y * 37 + js + d];
                a0 = fmaf(v, LO[2 * d + 1], a0);
                a1 = fmaf(v, LO[2 * d],     a1);
            }
            s1[y * 65 + 2 * m]     = a0;
            s1[y * 65 + 2 * m + 1] = a1;
        }
        __syncthreads();

        float* op = out + ((size_t)bc * 64 + xo) * 4096;
        for (int u = tid; u < 32 * 64; u += 256) {
            int z = u & 63, m = u >> 6;
            int js = m + 1;
            float a0 = 0.f, a1 = 0.f;
#pragma unroll
            for (int d = 0; d < 4; d++) {
                float v = s1[(js + d) * 65 + z];
                a0 = fmaf(v, LO[2 * d + 1], a0);
                a1 = fmaf(v, LO[2 * d],     a1);
            }
            op[(2 * m) * 64 + z]     = a0;
            op[(2 * m + 1) * 64 + z] = a1;
        }
        __syncthreads();
    }
}

// ---------------------------------------------------------------------------
// Channel mix, ALL 8 bands in one launch (blockIdx.y = band).
// ---------------------------------------------------------------------------
__global__ void chanmix_all(const float* __restrict__ in,
                            float* __restrict__ out, long long SBl,
                            const float* __restrict__ w0, const float* __restrict__ w1,
                            const float* __restrict__ w2, const float* __restrict__ w3,
                            const float* __restrict__ w4, const float* __restrict__ w5,
                            const float* __restrict__ w6, const float* __restrict__ w7) {
    __shared__ float s_in[320][32];
    int k = blockIdx.y;
    const float* w;
    switch (k) {
        case 0: w = w0; break; case 1: w = w1; break;
        case 2: w = w2; break; case 3: w = w3; break;
        case 4: w = w4; break; case 5: w = w5; break;
        case 6: w = w6; break; default: w = w7; break;
    }
    const float* bin  = in  + (long long)k * SBl;
    float*       bout = out + (long long)k * SBl;

    int lane = threadIdx.x;
    int ty   = threadIdx.y;
    int v    = blockIdx.x * 32 + lane;
    bool valid = v < NV;
    int vc = valid ? v : (NV - 1);

    for (int r = ty; r < 320; r += 8)
        s_in[r][lane] = bin[(long long)r * NV + vc];
    __syncthreads();

    float acc[5][8];
#pragma unroll
    for (int a = 0; a < 5; a++)
#pragma unroll
        for (int b = 0; b < 8; b++) acc[a][b] = 0.f;

#pragma unroll 2
    for (int i = 0; i < 40; i += 2) {
        float xv0[8], xv1[8];
#pragma unroll
        for (int b = 0; b < 8; b++) {
            xv0[b] = s_in[b * 40 + i][lane];
            xv1[b] = s_in[b * 40 + i + 1][lane];
        }
        float wv0[5], wv1[5];
#pragma unroll
        for (int oo = 0; oo < 5; oo++) {
            int o = ty + oo * 8;
            wv0[oo] = w[((long long)i * 40 + o) * NV + vc];
            wv1[oo] = w[((long long)(i + 1) * 40 + o) * NV + vc];
        }
#pragma unroll
        for (int oo = 0; oo < 5; oo++)
#pragma unroll
            for (int b = 0; b < 8; b++) {
                acc[oo][b] = fmaf(xv0[b], wv0[oo], acc[oo][b]);
                acc[oo][b] = fmaf(xv1[b], wv1[oo], acc[oo][b]);
            }
    }
    if (!valid) return;
#pragma unroll
    for (int oo = 0; oo < 5; oo++) {
        int o = ty + oo * 8;
#pragma unroll
        for (int b = 0; b < 8; b++)
            bout[((long long)b * 40 + o) * NV + v] = acc[oo][b];
    }
}

// ---------------------------------------------------------------------------
extern "C" void kernel_launch(void* const* d_in, const int* in_sizes, int n_in,
                              void* d_out, int out_size) {
    const float* x = (const float*)d_in[0];
    float* out = (float*)d_out;

    float *b1, *b2;
    cudaGetSymbolAddress((void**)&b1, g_buf1);
    cudaGetSymbolAddress((void**)&b2, g_buf2);

    const long long S2  = 6263360LL;   // 320*37*23*23 (per yz-band volume)
    const long long SBl = 3893440LL;   // 320*23*23*23 (per final band volume)

    auto g = [](unsigned t) { return (t + 255u) / 256u; };

    // --- Level-1 forward: fused yz (lo), then x (lo) ------------------------
    f1_yz<<<320 * 64, 256>>>(x, b1);                        // -> (320,64,37,37)
    { unsigned T = 320u * 1369u;                            // -> (320,37,37,37)
      dwt_s<64, 1369, false><<<g(T), 256>>>(b1, b2, nullptr, T); }

    // --- Level-2 forward: fused yz (4 bands), then x (lo+hi over all 4) -----
    f2_yz<<<320 * 37, 256>>>(b2, b1, S2);                   // -> 4x(320,37,23,23)
    { unsigned T = 1280u * 529u;                            // -> 8x(320,23,23,23)
      dwt_s<37, 529, true><<<g(T), 256>>>(b1, b2, b2 + 4 * SBl, T); }

    // --- Channel mix: all 8 bands in one launch (slot == weight index k) ----
    chanmix_all<<<dim3((NV + 31) / 32, 8), dim3(32, 8)>>>(
        b2, b1, SBl,
        (const float*)d_in[1], (const float*)d_in[2],
        (const float*)d_in[3], (const float*)d_in[4],
        (const float*)d_in[5], (const float*)d_in[6],
        (const float*)d_in[7], (const float*)d_in[8]);

    // --- Level-2 inverse: FUSED x+zy, register-streamed x-IDWT --------------
    i2x_zy<<<320 * 10, 256>>>(b1, b2, SBl);                 // -> (320,37,37,37)

    // --- Level-1 inverse: FUSED x+zy (lo), R9 form ---------------------------
    i1x_yz<<<320 * 16, 256>>>(b2, out);                     // -> (320,64,64,64)
}